// round 15
// baseline (speedup 1.0000x reference)
#include <cuda_runtime.h>
#include <stdint.h>

#define Bn 4096
#define Dn 16
#define Mn 4
#define Rn 2048
#define Cn 10
#define BT 32
#define WARPS 16
#define THREADS 512
#define RPW 128         // rules per warp
#define CHUNK 8
#define SSTRIDE 36      // banks (4j+row)%32: conflict-free both directions
#define EPSV 1e-9f

// scratch (module-load allocation, allowed)
__device__ uint4    g_soff4[Rn];     // 4 direct pre-scaled byte offsets
__device__ uint32_t g_soff1[Rn];     // 5th pre-scaled byte offset
__device__ float    g_cs[Rn * 12];   // folded consequents (+1.0 fsum, 0 pad)

__device__ __forceinline__ void ffma2(unsigned long long& acc,
                                      unsigned long long a,
                                      unsigned long long b) {
    asm("fma.rn.f32x2 %0, %1, %2, %0;" : "+l"(acc) : "l"(a), "l"(b));
}
__device__ __forceinline__ unsigned long long bcast2(float f) {
    unsigned long long r;
    asm("mov.b64 %0, {%1, %1};" : "=l"(r) : "f"(f));
    return r;
}

// ---------------------------------------------------------------------------
// prep: 8 rules per 256-thread CTA, smem-staged
// ---------------------------------------------------------------------------
__global__ void anfis_prep(const float* __restrict__ cons,
                           const int*   __restrict__ rules) {
    __shared__ float s[8 * 170];
    const int r0 = blockIdx.x * 8;
    const float* base = cons + (size_t)r0 * 170;
    for (int i = threadIdx.x; i < 8 * 170; i += 256) s[i] = base[i];
    __syncthreads();
    const int t = threadIdx.x;
    if (t < 80) {
        int rr = t / 10, c = t % 10;
        float a = 0.f;
#pragma unroll
        for (int j = 0; j < 17; j++) a += s[rr * 170 + j * 10 + c];
        g_cs[(size_t)(r0 + rr) * 12 + c] = a;
    } else if (t < 96) {
        int rr = (t - 80) >> 1;
        // slot [10] = 1.0 -> fsum rides the FFMA2 stream; [11] = 0
        g_cs[(size_t)(r0 + rr) * 12 + 10 + ((t - 80) & 1)] =
            ((t - 80) & 1) ? 0.f : 1.f;
    } else if (t < 104) {
        int rr = t - 96;
        const int* rp = rules + (size_t)(r0 + rr) * Dn;
        // groups: (0-2),(3-5),(6-8),(9-11) -> 64 entries; (12-15) -> 256
        uint32_t i0 = ((uint32_t)rp[0] & 3u) | (((uint32_t)rp[1] & 3u) << 2)
                    | (((uint32_t)rp[2] & 3u) << 4);
        uint32_t i1 = ((uint32_t)rp[3] & 3u) | (((uint32_t)rp[4] & 3u) << 2)
                    | (((uint32_t)rp[5] & 3u) << 4);
        uint32_t i2 = ((uint32_t)rp[6] & 3u) | (((uint32_t)rp[7] & 3u) << 2)
                    | (((uint32_t)rp[8] & 3u) << 4);
        uint32_t i3 = ((uint32_t)rp[9] & 3u) | (((uint32_t)rp[10] & 3u) << 2)
                    | (((uint32_t)rp[11] & 3u) << 4);
        uint32_t i4 = ((uint32_t)rp[12] & 3u) | (((uint32_t)rp[13] & 3u) << 2)
                    | (((uint32_t)rp[14] & 3u) << 4) | (((uint32_t)rp[15] & 3u) << 6);
        uint4 o;
        o.x =           i0  * 128u;
        o.y = ( 64u  + i1)  * 128u;
        o.z = (128u  + i2)  * 128u;
        o.w = (192u  + i3)  * 128u;
        g_soff4[r0 + rr] = o;
        g_soff1[r0 + rr] = (256u + i4) * 128u;
    }
}

// ---------------------------------------------------------------------------
// main: one 512-thread CTA per 32-row batch tile, all 2048 rules.
// All-smem loop; direct pre-scaled u32 offsets (zero unpack ALU).
// ---------------------------------------------------------------------------
// smem floats: tbl 512*32=16384 | stage 16*8*36=4608 (overlays mf 2048 +
//   pair 1024 at build) | csm 2048*12=24576 | soff4 8192 | soff1 2048 |
//   xs 512 | red 384 | inv 32  => 56736 floats = 226944 B
#define STAGE_FLOATS (WARPS * CHUNK * SSTRIDE)
#define SMEM_FLOATS  (16384 + STAGE_FLOATS + 24576 + 8192 + 2048 + 512 + 384 + 32)
#define SMEM_BYTES   (SMEM_FLOATS * 4)

__global__ void __launch_bounds__(THREADS, 1)
anfis_main(const float* __restrict__ x,
           const float* __restrict__ centers,
           const float* __restrict__ widths,
           float* __restrict__ out,     // (B, C)
           float* __restrict__ nf,      // (B, R)
           float* __restrict__ xext,    // (B, D+1)
           int write_aux) {
    extern __shared__ float sm[];
    float* tbl   = sm;                              // 512*32
    float* stage = tbl + 16384;                     // 16*8*36
    float* csm   = stage + STAGE_FLOATS;            // 2048*12 (16B aligned)
    uint4* so4   = (uint4*)(csm + 24576);           // 2048 uint4 (16B aligned)
    uint32_t* so1 = (uint32_t*)(so4 + 2048);        // 2048 u32
    float* xs    = (float*)(so1 + 2048);            // 32*16
    float* red   = xs + 512;                        // 12*32
    float* inv_s = red + 384;                       // 32
    float* mf    = stage;                           // overlay (build) 64*32
    float* pair  = stage + 2048;                    // overlay (build) 32*32

    const int tid  = threadIdx.x;
    const int w    = tid >> 5;
    const int lane = tid & 31;
    const int b0   = blockIdx.x * BT;

    // ---- build phase ----
    if (tid < BT * Dn)
        xs[tid] = x[(size_t)b0 * Dn + tid];
    if (tid < 384) red[tid] = 0.f;

    // stage consequents + offsets into smem (coalesced, wide)
    {
        const float4* src = (const float4*)g_cs;
        float4* dst = (float4*)csm;
#pragma unroll
        for (int k = 0; k < 12; k++)
            dst[tid + k * THREADS] = src[tid + k * THREADS];   // 6144 float4
#pragma unroll
        for (int k = 0; k < 4; k++)
            so4[tid + k * THREADS] = g_soff4[tid + k * THREADS];
        const uint4* s1src = (const uint4*)g_soff1;
        uint4* s1dst = (uint4*)so1;
        s1dst[tid] = s1src[tid];                               // 512 uint4
    }
    __syncthreads();

    // membership values
#pragma unroll
    for (int e = tid; e < 64 * 32; e += THREADS) {
        int dm = e >> 5, b = e & 31;
        int d = dm >> 2, m = dm & 3;
        float cc = centers[d * Mn + m];
        float ww = widths[d * Mn + m];
        float df = xs[b * Dn + d] - cc;
        mf[dm * 32 + b] = expf(-df * df / (2.f * ww * ww));
    }
    __syncthreads();

    // groups 0-3: 3 dims each, 64 entries
    for (int pp = w; pp < 256; pp += WARPS) {
        int g = pp >> 6, idx = pp & 63;
        tbl[pp * 32 + lane] =
            mf[((3*g + 0) * 4 + ( idx       & 3)) * 32 + lane] *
            mf[((3*g + 1) * 4 + ((idx >> 2) & 3)) * 32 + lane] *
            mf[((3*g + 2) * 4 + ( idx >> 4     )) * 32 + lane];
    }
    // pair tables for group 4 (dims 12-13, 14-15)
    for (int pp = w; pp < 32; pp += WARPS) {
        int grp = pp >> 4, i2 = pp & 15;
        int d0 = 12 + grp * 2;
        pair[pp * 32 + lane] =
            mf[(d0     * 4 + (i2 & 3))  * 32 + lane] *
            mf[((d0+1) * 4 + (i2 >> 2)) * 32 + lane];
    }
    __syncthreads();
    // group 4: 4 dims, 256 entries (table base 256)
    for (int pp = w; pp < 256; pp += WARPS) {
        tbl[(256 + pp) * 32 + lane] =
            pair[(pp & 15) * 32 + lane] * pair[(16 + (pp >> 4)) * 32 + lane];
    }
    __syncthreads();   // stage region free from here

    // ---- main loop: 128 rules/warp in chunks of 8, all-smem, no unpack ----
    const char* tbB = (const char*)tbl + lane * 4;
    const ulonglong2* cs2 = (const ulonglong2*)csm;
    const int rbase = w * RPW;
    float* stg = stage + w * (CHUNK * SSTRIDE);

    unsigned long long a01 = 0, a23 = 0, a45 = 0, a67 = 0, a89 = 0, aSF = 0;

    for (int ch = 0; ch < RPW / CHUNK; ch++) {
        const int r0 = rbase + ch * CHUNK;
#pragma unroll
        for (int rl = 0; rl < CHUNK; rl++) {
            const int r = r0 + rl;
            const uint4 o = so4[r];                   // LDS.128 broadcast
            const uint32_t o4 = so1[r];               // LDS.32 broadcast
            float f0 = *(const float*)(tbB + o.x);
            float f1 = *(const float*)(tbB + o.y);
            float f2 = *(const float*)(tbB + o.z);
            float f3 = *(const float*)(tbB + o.w);
            float f4 = *(const float*)(tbB + o4);
            float f = ((f0 * f1) * (f2 * f3)) * f4;
            stg[rl * SSTRIDE + lane] = f;
            unsigned long long fp = bcast2(f);
            ulonglong2 v0 = cs2[r * 3 + 0];           // LDS.128 broadcast
            ulonglong2 v1 = cs2[r * 3 + 1];
            ulonglong2 v2 = cs2[r * 3 + 2];
            ffma2(a01, fp, v0.x); ffma2(a23, fp, v0.y);
            ffma2(a45, fp, v1.x); ffma2(a67, fp, v1.y);
            ffma2(a89, fp, v2.x); ffma2(aSF, fp, v2.y);   // .lo = fsum
        }
        __syncwarp();
        if (write_aux) {
            // transposed flush: 4 rows x 8 rules per pass, banks (4j+row)%32
#pragma unroll
            for (int t2 = 0; t2 < 8; t2++) {
                int row = 4 * t2 + (lane >> 3);   // batch row 0..31
                int j = lane & 7;                 // rule-in-chunk 0..7
                nf[(size_t)(b0 + row) * Rn + r0 + j] = stg[j * SSTRIDE + row];
            }
        }
        __syncwarp();
    }

    // ---- CTA reduction (smem atomics, one-time) ----
    {
        union { unsigned long long u; float2 f; } c0, c1, c2, c3, c4, c5;
        c0.u = a01; c1.u = a23; c2.u = a45; c3.u = a67; c4.u = a89; c5.u = aSF;
        atomicAdd(&red[ 0 * 32 + lane], c0.f.x);
        atomicAdd(&red[ 1 * 32 + lane], c0.f.y);
        atomicAdd(&red[ 2 * 32 + lane], c1.f.x);
        atomicAdd(&red[ 3 * 32 + lane], c1.f.y);
        atomicAdd(&red[ 4 * 32 + lane], c2.f.x);
        atomicAdd(&red[ 5 * 32 + lane], c2.f.y);
        atomicAdd(&red[ 6 * 32 + lane], c3.f.x);
        atomicAdd(&red[ 7 * 32 + lane], c3.f.y);
        atomicAdd(&red[ 8 * 32 + lane], c4.f.x);
        atomicAdd(&red[ 9 * 32 + lane], c4.f.y);
        atomicAdd(&red[10 * 32 + lane], c5.f.x);
    }
    __syncthreads();

    if (tid < 32)
        inv_s[tid] = 1.f / (red[10 * 32 + tid] + EPSV);
    __syncthreads();

    // out[b][c] = sx[b] * inv[b] * acc[b][c]
    if (tid < BT * Cn) {
        int b = tid & 31, c = tid >> 5;
        float s = 1.f;
#pragma unroll
        for (int d = 0; d < Dn; d++) s += xs[b * Dn + d];
        out[(size_t)(b0 + b) * Cn + c] = s * inv_s[b] * red[c * 32 + b];
    }

    if (write_aux) {
        // xext: 544 elements, strided (THREADS=512 < 544)
        for (int i = tid; i < BT * (Dn + 1); i += THREADS) {
            int b = i / (Dn + 1), j = i % (Dn + 1);
            xext[(size_t)(b0 + b) * (Dn + 1) + j] =
                (j < Dn) ? xs[b * Dn + j] : 1.f;
        }
        // in-place normalize of this CTA's nf region (L2-resident), float4
        __syncthreads();
        float4* p = (float4*)(nf + (size_t)b0 * Rn);
#pragma unroll
        for (int k = 0; k < 32; k++) {
            int i = tid + k * THREADS;          // 16384 float4 = 32 rows x 512
            float iv = inv_s[i >> 9];           // Rn/4 = 512 float4 per row
            float4 v = p[i];
            v.x *= iv; v.y *= iv; v.z *= iv; v.w *= iv;
            p[i] = v;
        }
    }
}

// ---------------------------------------------------------------------------
extern "C" void kernel_launch(void* const* d_in, const int* in_sizes, int n_in,
                              void* d_out, int out_size) {
    const float* x       = (const float*)d_in[0];
    const float* centers = (const float*)d_in[1];
    const float* widths  = (const float*)d_in[2];
    const float* cons    = (const float*)d_in[3];
    const int*   rules   = (const int*)d_in[4];

    float* out = (float*)d_out;
    const long total = (long)Bn * Cn + (long)Bn * Rn + (long)Bn * (Dn + 1);
    const int write_aux = (out_size >= total) ? 1 : 0;
    float* nf   = out + (size_t)Bn * Cn;
    float* xext = nf + (size_t)Bn * Rn;

    anfis_prep<<<Rn / 8, 256>>>(cons, rules);

    cudaFuncSetAttribute(anfis_main, cudaFuncAttributeMaxDynamicSharedMemorySize,
                         SMEM_BYTES);
    anfis_main<<<Bn / BT, THREADS, SMEM_BYTES>>>(x, centers, widths,
                                                 out, nf, xext, write_aux);
}

// round 16
// speedup vs baseline: 1.0268x; 1.0268x over previous
#include <cuda_runtime.h>
#include <stdint.h>

#define Bn 4096
#define Dn 16
#define Mn 4
#define Rn 2048
#define Cn 10
#define BT 32
#define WARPS 16
#define THREADS 512
#define RPW 128         // rules per warp
#define CHUNK 16
#define SSTRIDE 33
#define EPSV 1e-9f

// scratch (module-load allocation, allowed)
__device__ uint2 g_sidx2[Rn];    // pre-scaled u16 offsets o0|o1, o2|o3
__device__ float g_cs[Rn * 12];  // c0..c9, 1.0 (fsum), bits(o4)

__device__ __forceinline__ void ffma2(unsigned long long& acc,
                                      unsigned long long a,
                                      unsigned long long b) {
    asm("fma.rn.f32x2 %0, %1, %2, %0;" : "+l"(acc) : "l"(a), "l"(b));
}
__device__ __forceinline__ unsigned long long bcast2(float f) {
    unsigned long long r;
    asm("mov.b64 %0, {%1, %1};" : "=l"(r) : "f"(f));
    return r;
}

// ---------------------------------------------------------------------------
// prep: 8 rules per 256-thread CTA, smem-staged
// ---------------------------------------------------------------------------
__global__ void anfis_prep(const float* __restrict__ cons,
                           const int*   __restrict__ rules) {
    __shared__ float s[8 * 170];
    const int r0 = blockIdx.x * 8;
    const float* base = cons + (size_t)r0 * 170;
    for (int i = threadIdx.x; i < 8 * 170; i += 256) s[i] = base[i];
    __syncthreads();
    const int t = threadIdx.x;
    if (t < 80) {
        int rr = t / 10, c = t % 10;
        float a = 0.f;
#pragma unroll
        for (int j = 0; j < 17; j++) a += s[rr * 170 + j * 10 + c];
        g_cs[(size_t)(r0 + rr) * 12 + c] = a;
    } else if (t < 88) {
        // slot [10] = 1.0: fsum rides the FFMA2 stream
        int rr = t - 80;
        g_cs[(size_t)(r0 + rr) * 12 + 10] = 1.f;
    } else if (t < 96) {
        // slot [11] = bits(o4): 5th table offset rides the cs LDS.128
        int rr = t - 88;
        const int* rp = rules + (size_t)(r0 + rr) * Dn;
        uint32_t i4 = ((uint32_t)rp[12] & 3u) | (((uint32_t)rp[13] & 3u) << 2)
                    | (((uint32_t)rp[14] & 3u) << 4) | (((uint32_t)rp[15] & 3u) << 6);
        uint32_t o4 = (256u + i4) * 128u;
        g_cs[(size_t)(r0 + rr) * 12 + 11] = __uint_as_float(o4);
    } else if (t < 104) {
        int rr = t - 96;
        const int* rp = rules + (size_t)(r0 + rr) * Dn;
        // groups: (0-2),(3-5),(6-8),(9-11) -> 64 entries each
        uint32_t i0 = ((uint32_t)rp[0] & 3u) | (((uint32_t)rp[1] & 3u) << 2)
                    | (((uint32_t)rp[2] & 3u) << 4);
        uint32_t i1 = ((uint32_t)rp[3] & 3u) | (((uint32_t)rp[4] & 3u) << 2)
                    | (((uint32_t)rp[5] & 3u) << 4);
        uint32_t i2 = ((uint32_t)rp[6] & 3u) | (((uint32_t)rp[7] & 3u) << 2)
                    | (((uint32_t)rp[8] & 3u) << 4);
        uint32_t i3 = ((uint32_t)rp[9] & 3u) | (((uint32_t)rp[10] & 3u) << 2)
                    | (((uint32_t)rp[11] & 3u) << 4);
        uint32_t o0 =           i0 * 128u;
        uint32_t o1 = ( 64u  + i1) * 128u;
        uint32_t o2 = (128u  + i2) * 128u;
        uint32_t o3 = (192u  + i3) * 128u;
        uint2 oa;
        oa.x = o0 | (o1 << 16);
        oa.y = o2 | (o3 << 16);
        g_sidx2[r0 + rr] = oa;
    }
}

// ---------------------------------------------------------------------------
// main: one 512-thread CTA per 32-row batch tile, all 2048 rules.
// All-smem loop; 12 MIO ops/rule (o4 embedded in the cs stream).
// ---------------------------------------------------------------------------
// smem floats: tbl 512*32=16384 | stage 16*16*33=8448 (overlays mf 2048 +
//   pair 1024 at build) | csm 2048*12=24576 | sofA 4096 |
//   xs 512 | red 384 | inv 32   => 54432 floats = 217728 B < 227 KB
#define STAGE_FLOATS (WARPS * CHUNK * SSTRIDE)
#define SMEM_FLOATS  (16384 + STAGE_FLOATS + 24576 + 4096 + 512 + 384 + 32)
#define SMEM_BYTES   (SMEM_FLOATS * 4)

__global__ void __launch_bounds__(THREADS, 1)
anfis_main(const float* __restrict__ x,
           const float* __restrict__ centers,
           const float* __restrict__ widths,
           float* __restrict__ out,     // (B, C)
           float* __restrict__ nf,      // (B, R)
           float* __restrict__ xext,    // (B, D+1)
           int write_aux) {
    extern __shared__ float sm[];
    float* tbl   = sm;                              // 512*32
    float* stage = tbl + 16384;                     // 16*16*33
    float* csm   = stage + STAGE_FLOATS;            // 2048*12 (16B aligned)
    uint2* sofA  = (uint2*)(csm + 24576);           // 2048 uint2
    float* xs    = (float*)(sofA + 2048);           // 32*16
    float* red   = xs + 512;                        // 12*32
    float* inv_s = red + 384;                       // 32
    float* mf    = stage;                           // overlay (build) 64*32
    float* pair  = stage + 2048;                    // overlay (build) 32*32

    const int tid  = threadIdx.x;
    const int w    = tid >> 5;
    const int lane = tid & 31;
    const int b0   = blockIdx.x * BT;

    // ---- build phase ----
    if (tid < BT * Dn)
        xs[tid] = x[(size_t)b0 * Dn + tid];
    if (tid < 384) red[tid] = 0.f;

    // stage consequents + offsets into smem (coalesced, wide)
    {
        const float4* src = (const float4*)g_cs;
        float4* dst = (float4*)csm;
#pragma unroll
        for (int k = 0; k < 12; k++)
            dst[tid + k * THREADS] = src[tid + k * THREADS];   // 6144 float4
#pragma unroll
        for (int k = 0; k < 4; k++)
            sofA[tid + k * THREADS] = g_sidx2[tid + k * THREADS];
    }
    __syncthreads();

    // membership values
#pragma unroll
    for (int e = tid; e < 64 * 32; e += THREADS) {
        int dm = e >> 5, b = e & 31;
        int d = dm >> 2, m = dm & 3;
        float cc = centers[d * Mn + m];
        float ww = widths[d * Mn + m];
        float df = xs[b * Dn + d] - cc;
        mf[dm * 32 + b] = expf(-df * df / (2.f * ww * ww));
    }
    __syncthreads();

    // groups 0-3: 3 dims each, 64 entries
    for (int pp = w; pp < 256; pp += WARPS) {
        int g = pp >> 6, idx = pp & 63;
        tbl[pp * 32 + lane] =
            mf[((3*g + 0) * 4 + ( idx       & 3)) * 32 + lane] *
            mf[((3*g + 1) * 4 + ((idx >> 2) & 3)) * 32 + lane] *
            mf[((3*g + 2) * 4 + ( idx >> 4     )) * 32 + lane];
    }
    // pair tables for group 4 (dims 12-13, 14-15)
    for (int pp = w; pp < 32; pp += WARPS) {
        int grp = pp >> 4, i2 = pp & 15;
        int d0 = 12 + grp * 2;
        pair[pp * 32 + lane] =
            mf[(d0     * 4 + (i2 & 3))  * 32 + lane] *
            mf[((d0+1) * 4 + (i2 >> 2)) * 32 + lane];
    }
    __syncthreads();
    // group 4: 4 dims, 256 entries (table base 256)
    for (int pp = w; pp < 256; pp += WARPS) {
        tbl[(256 + pp) * 32 + lane] =
            pair[(pp & 15) * 32 + lane] * pair[(16 + (pp >> 4)) * 32 + lane];
    }
    __syncthreads();   // stage region free from here

    // ---- main loop: 128 rules/warp in chunks of 16, all-smem ----
    const char* tbB = (const char*)tbl + lane * 4;
    const ulonglong2* cs2 = (const ulonglong2*)csm;
    const int rbase = w * RPW;
    float* stg = stage + w * (CHUNK * SSTRIDE);

    unsigned long long a01 = 0, a23 = 0, a45 = 0, a67 = 0, a89 = 0, aSF = 0;

    for (int ch = 0; ch < RPW / CHUNK; ch++) {
        const int r0 = rbase + ch * CHUNK;
#pragma unroll
        for (int rl = 0; rl < CHUNK; rl++) {
            const int r = r0 + rl;
            // cs + o4: three LDS.128 broadcasts
            ulonglong2 v0 = cs2[r * 3 + 0];
            ulonglong2 v1 = cs2[r * 3 + 1];
            ulonglong2 v2 = cs2[r * 3 + 2];       // .y = (1.0, bits(o4))
            const uint2 oa = sofA[r];             // LDS.64 broadcast
            const uint32_t o4 = (uint32_t)(v2.y >> 32);
            float f0 = *(const float*)(tbB + (oa.x & 0xFFFFu));
            float f1 = *(const float*)(tbB + (oa.x >> 16));
            float f2 = *(const float*)(tbB + (oa.y & 0xFFFFu));
            float f3 = *(const float*)(tbB + (oa.y >> 16));
            float f4 = *(const float*)(tbB + o4);
            float f = ((f0 * f1) * (f2 * f3)) * f4;
            stg[rl * SSTRIDE + lane] = f;
            unsigned long long fp = bcast2(f);
            ffma2(a01, fp, v0.x); ffma2(a23, fp, v0.y);
            ffma2(a45, fp, v1.x); ffma2(a67, fp, v1.y);
            ffma2(a89, fp, v2.x); ffma2(aSF, fp, v2.y);   // .lo = fsum
        }
        __syncwarp();
        if (write_aux) {
            // transposed flush: 2 rows x 16 rules per pass, 64B stores
#pragma unroll
            for (int t2 = 0; t2 < 16; t2++) {
                int row = 2 * t2 + (lane >> 4);   // batch row 0..31
                int j = lane & 15;                // rule-in-chunk 0..15
                nf[(size_t)(b0 + row) * Rn + r0 + j] = stg[j * SSTRIDE + row];
            }
        }
        __syncwarp();
    }

    // ---- CTA reduction (smem atomics, one-time) ----
    {
        union { unsigned long long u; float2 f; } c0, c1, c2, c3, c4, c5;
        c0.u = a01; c1.u = a23; c2.u = a45; c3.u = a67; c4.u = a89; c5.u = aSF;
        atomicAdd(&red[ 0 * 32 + lane], c0.f.x);
        atomicAdd(&red[ 1 * 32 + lane], c0.f.y);
        atomicAdd(&red[ 2 * 32 + lane], c1.f.x);
        atomicAdd(&red[ 3 * 32 + lane], c1.f.y);
        atomicAdd(&red[ 4 * 32 + lane], c2.f.x);
        atomicAdd(&red[ 5 * 32 + lane], c2.f.y);
        atomicAdd(&red[ 6 * 32 + lane], c3.f.x);
        atomicAdd(&red[ 7 * 32 + lane], c3.f.y);
        atomicAdd(&red[ 8 * 32 + lane], c4.f.x);
        atomicAdd(&red[ 9 * 32 + lane], c4.f.y);
        atomicAdd(&red[10 * 32 + lane], c5.f.x);
    }
    __syncthreads();

    if (tid < 32)
        inv_s[tid] = 1.f / (red[10 * 32 + tid] + EPSV);
    __syncthreads();

    // out[b][c] = sx[b] * inv[b] * acc[b][c]
    if (tid < BT * Cn) {
        int b = tid & 31, c = tid >> 5;
        float s = 1.f;
#pragma unroll
        for (int d = 0; d < Dn; d++) s += xs[b * Dn + d];
        out[(size_t)(b0 + b) * Cn + c] = s * inv_s[b] * red[c * 32 + b];
    }

    if (write_aux) {
        // xext: 544 elements, strided (THREADS=512 < 544)
        for (int i = tid; i < BT * (Dn + 1); i += THREADS) {
            int b = i / (Dn + 1), j = i % (Dn + 1);
            xext[(size_t)(b0 + b) * (Dn + 1) + j] =
                (j < Dn) ? xs[b * Dn + j] : 1.f;
        }
        // in-place normalize of this CTA's nf region (L2-resident), float4
        __syncthreads();
        float4* p = (float4*)(nf + (size_t)b0 * Rn);
#pragma unroll
        for (int k = 0; k < 32; k++) {
            int i = tid + k * THREADS;          // 16384 float4 = 32 rows x 512
            float iv = inv_s[i >> 9];           // Rn/4 = 512 float4 per row
            float4 v = p[i];
            v.x *= iv; v.y *= iv; v.z *= iv; v.w *= iv;
            p[i] = v;
        }
    }
}

// ---------------------------------------------------------------------------
extern "C" void kernel_launch(void* const* d_in, const int* in_sizes, int n_in,
                              void* d_out, int out_size) {
    const float* x       = (const float*)d_in[0];
    const float* centers = (const float*)d_in[1];
    const float* widths  = (const float*)d_in[2];
    const float* cons    = (const float*)d_in[3];
    const int*   rules   = (const int*)d_in[4];

    float* out = (float*)d_out;
    const long total = (long)Bn * Cn + (long)Bn * Rn + (long)Bn * (Dn + 1);
    const int write_aux = (out_size >= total) ? 1 : 0;
    float* nf   = out + (size_t)Bn * Cn;
    float* xext = nf + (size_t)Bn * Rn;

    anfis_prep<<<Rn / 8, 256>>>(cons, rules);

    cudaFuncSetAttribute(anfis_main, cudaFuncAttributeMaxDynamicSharedMemorySize,
                         SMEM_BYTES);
    anfis_main<<<Bn / BT, THREADS, SMEM_BYTES>>>(x, centers, widths,
                                                 out, nf, xext, write_aux);
}